// round 1
// baseline (speedup 1.0000x reference)
#include <cuda_runtime.h>

#define T_STEPS 32768
#define DIM     256
#define HID     64
#define G3      192      // 3*HID
#define JJ      1024     // J*J
#define CH      8        // gi prefetch chunk (must be even)

// Scratch (no runtime allocation allowed)
__device__ float g_gi[(T_STEPS + CH) * G3];   // ~25 MB, padded for prefetch overrun
__device__ float g_hs[T_STEPS * HID];         // 8 MB

typedef unsigned long long u64;

// ---------------- f32x2 helpers ----------------
__device__ __forceinline__ u64 pack2(float lo, float hi) {
    u64 r; asm("mov.b64 %0, {%1, %2};" : "=l"(r) : "f"(lo), "f"(hi)); return r;
}
__device__ __forceinline__ void unpack2(u64 v, float& lo, float& hi) {
    asm("mov.b64 {%0, %1}, %2;" : "=f"(lo), "=f"(hi) : "l"(v));
}
__device__ __forceinline__ u64 fma2(u64 a, u64 b, u64 c) {
    u64 d; asm("fma.rn.f32x2 %0, %1, %2, %3;" : "=l"(d) : "l"(a), "l"(b), "l"(c)); return d;
}
__device__ __forceinline__ u64 add2(u64 a, u64 b) {
    u64 d; asm("add.rn.f32x2 %0, %1, %2;" : "=l"(d) : "l"(a), "l"(b)); return d;
}
__device__ __forceinline__ float red2(u64 v) { float a, b; unpack2(v, a, b); return a + b; }

__device__ __forceinline__ float sigf(float x) {
    return __fdividef(1.0f, 1.0f + __expf(-x));
}
__device__ __forceinline__ float tanh_fast(float x) {
    return 1.0f - __fdividef(2.0f, __expf(2.0f * x) + 1.0f);
}

// =====================================================================
// Kernel 1: gi[t,g] = b_ih[g] + sum_d states[t, d] * w_ih[g, d]
// grid 1024 blocks x 192 threads, 32 t-rows per block, f32x2 over t-pairs.
// =====================================================================
__global__ __launch_bounds__(192) void gi_kernel(const float* __restrict__ states,
                                                 const float* __restrict__ w_ih,
                                                 const float* __restrict__ b_ih) {
    __shared__ float xs[32][36];           // [dd][tt], padded, rows 16B aligned
    const int tid = threadIdx.x;           // = g (0..191)
    const int t0  = blockIdx.x * 32;

    u64 acc[16];
#pragma unroll
    for (int q = 0; q < 16; q++) acc[q] = 0ULL;

    const float* wrow = w_ih + (size_t)tid * DIM;

    for (int d0 = 0; d0 < DIM; d0 += 32) {
        __syncthreads();
        for (int i = tid; i < 1024; i += 192) {
            int dd = i & 31, tt = i >> 5;
            xs[dd][tt] = states[(size_t)(t0 + tt) * (DIM + 3) + d0 + dd];
        }
        __syncthreads();

        float wv[32];
#pragma unroll
        for (int dd = 0; dd < 32; dd++) wv[dd] = wrow[d0 + dd];

#pragma unroll
        for (int dd = 0; dd < 32; dd++) {
            u64 wp = pack2(wv[dd], wv[dd]);
            const float4* xr = (const float4*)xs[dd];
#pragma unroll
            for (int q = 0; q < 8; q++) {
                float4 v = xr[q];
                acc[2 * q + 0] = fma2(pack2(v.x, v.y), wp, acc[2 * q + 0]);
                acc[2 * q + 1] = fma2(pack2(v.z, v.w), wp, acc[2 * q + 1]);
            }
        }
    }

    const float b = b_ih[tid];
#pragma unroll
    for (int q = 0; q < 16; q++) {
        float a, c; unpack2(acc[q], a, c);
        g_gi[(size_t)(t0 + 2 * q + 0) * G3 + tid] = a + b;
        g_gi[(size_t)(t0 + 2 * q + 1) * G3 + tid] = c + b;
    }
}

// =====================================================================
// Kernel 2: the sequential GRU scan. ONE block, 128 threads (4 warps).
// Lane pairs (2m, 2m+1) own h-index j = warp*16 + m:
//   even lane: r-dot (32 FFMA2) + z-dot lower half (16 FFMA2)
//   odd  lane: n-dot (32 FFMA2) + z-dot upper half (16 FFMA2)
// z halves and r exchanged via shfl.xor(1). One __syncthreads per step
// (double-buffered h in shared).
// =====================================================================
__global__ __launch_bounds__(128, 1) void scan_kernel(const float* __restrict__ h0,
                                                      const float* __restrict__ w_hh,
                                                      const float* __restrict__ b_hh,
                                                      float* __restrict__ h_final) {
    __shared__ float hbuf[2][HID];

    const int tid  = threadIdx.x;
    const int w    = tid >> 5;
    const int lane = tid & 31;
    const int m    = lane >> 1;
    const int j    = w * 16 + m;
    const int odd  = lane & 1;

    // Per-thread weight rows in registers (f32x2 packed)
    u64 wmain[32], wz[16];
    {
        const u64* rm = (const u64*)(w_hh + (size_t)(odd ? (128 + j) : j) * HID);
#pragma unroll
        for (int k = 0; k < 32; k++) wmain[k] = rm[k];
        const u64* rz = (const u64*)(w_hh + (size_t)(64 + j) * HID) + (odd ? 16 : 0);
#pragma unroll
        for (int k = 0; k < 16; k++) wz[k] = rz[k];
    }
    const float bmain = b_hh[odd ? (128 + j) : j];
    const float bz    = b_hh[64 + j];

    if (tid < HID) hbuf[0][tid] = h0[tid];

    const float* gmain = g_gi + (odd ? (128 + j) : j);
    const float* gzp   = g_gi + 64 + j;

    float gm_nxt[CH], gz_nxt[CH];
#pragma unroll
    for (int k = 0; k < CH; k++) {
        gm_nxt[k] = gmain[(size_t)k * G3];
        gz_nxt[k] = odd ? gzp[(size_t)k * G3] : 0.0f;
    }
    __syncthreads();

    for (int s0 = 0; s0 < T_STEPS; s0 += CH) {
        float gm[CH], gzc[CH];
#pragma unroll
        for (int k = 0; k < CH; k++) { gm[k] = gm_nxt[k]; gzc[k] = gz_nxt[k]; }
        {   // prefetch next chunk (padded tail is harmless)
            const size_t nb = (size_t)(s0 + CH) * G3;
#pragma unroll
            for (int k = 0; k < CH; k++) {
                gm_nxt[k] = gmain[nb + (size_t)k * G3];
                gz_nxt[k] = odd ? gzp[nb + (size_t)k * G3] : 0.0f;
            }
        }

#pragma unroll
        for (int ss = 0; ss < CH; ss++) {
            const int p = ss & 1;

            const float4* h4 = (const float4*)hbuf[p];
            u64 a0 = 0, a1 = 0, a2 = 0, a3 = 0;
#pragma unroll
            for (int q = 0; q < 8; q++) {
                float4 v0 = h4[2 * q];
                float4 v1 = h4[2 * q + 1];
                a0 = fma2(wmain[4 * q + 0], pack2(v0.x, v0.y), a0);
                a1 = fma2(wmain[4 * q + 1], pack2(v0.z, v0.w), a1);
                a2 = fma2(wmain[4 * q + 2], pack2(v1.x, v1.y), a2);
                a3 = fma2(wmain[4 * q + 3], pack2(v1.z, v1.w), a3);
            }
            // z-dot half: lane-dependent shared address (avoids runtime reg indexing)
            const u64* hzp = (const u64*)(hbuf[p] + (odd ? 32 : 0));
            u64 z0 = 0, z1 = 0;
#pragma unroll
            for (int k = 0; k < 16; k += 2) {
                z0 = fma2(wz[k],     hzp[k],     z0);
                z1 = fma2(wz[k + 1], hzp[k + 1], z1);
            }
            const float hprev = hbuf[p][j];

            const float smain = red2(add2(add2(a0, a1), add2(a2, a3)));
            const float zh    = red2(add2(z0, z1));
            const float zfull = zh + __shfl_xor_sync(0xffffffffu, zh, 1);

            // even lane: real r; odd lane garbage (unused after shfl)
            const float r_e = sigf(gm[ss] + smain + bmain);
            const float r   = __shfl_xor_sync(0xffffffffu, r_e, 1);  // odd receives r

            const float z    = sigf(gzc[ss] + zfull + bz);           // valid on odd
            const float ghn  = smain + bmain;                        // odd: n-gate gh (incl b)
            const float n    = tanh_fast(gm[ss] + r * ghn);          // valid on odd
            const float hnew = n + z * (hprev - n);

            if (odd) {
                hbuf[p ^ 1][j] = hnew;
                g_hs[(size_t)(s0 + ss) * HID + j] = hnew;
            }
            __syncthreads();
        }
    }
    // T_STEPS % CH == 0 and CH even -> final h lives in hbuf[0]
    if (tid < HID) h_final[tid] = hbuf[0][tid];
}

// =====================================================================
// Kernel 3: logits[t,o] = mask[o] ? hs[t,:]·w_out[o,:] + b_out[o] : -1e9
// grid (512, 16), 256 threads, 64x64 tile, 4x4 register micro-tile.
// =====================================================================
__global__ __launch_bounds__(256) void out_kernel(const float* __restrict__ w_out,
                                                  const float* __restrict__ b_out,
                                                  const int* __restrict__ mask,
                                                  float* __restrict__ out) {
    __shared__ float hs_sh[64][68];   // [k][t]
    __shared__ float w_sh[64][68];    // [k][o]

    const int tid = threadIdx.x;
    const int t0  = blockIdx.x * 64;
    const int o0  = blockIdx.y * 64;

#pragma unroll
    for (int q = 0; q < 4; q++) {
        int i  = tid + q * 256;      // 0..1023
        int rr = i >> 4;             // row within tile (t or o)
        int kq = i & 15;             // float4 index along k
        float4 v = *(const float4*)(g_hs + (size_t)(t0 + rr) * HID + kq * 4);
        hs_sh[kq * 4 + 0][rr] = v.x;
        hs_sh[kq * 4 + 1][rr] = v.y;
        hs_sh[kq * 4 + 2][rr] = v.z;
        hs_sh[kq * 4 + 3][rr] = v.w;
        float4 wv = *(const float4*)(w_out + (size_t)(o0 + rr) * HID + kq * 4);
        w_sh[kq * 4 + 0][rr] = wv.x;
        w_sh[kq * 4 + 1][rr] = wv.y;
        w_sh[kq * 4 + 2][rr] = wv.z;
        w_sh[kq * 4 + 3][rr] = wv.w;
    }
    __syncthreads();

    const int oo0 = (tid & 15) * 4;
    const int tt0 = (tid >> 4) * 4;

    float acc[4][4];
#pragma unroll
    for (int i = 0; i < 4; i++)
#pragma unroll
        for (int jj2 = 0; jj2 < 4; jj2++) acc[i][jj2] = 0.0f;

#pragma unroll
    for (int k = 0; k < 64; k++) {
        float4 a = *(const float4*)&hs_sh[k][tt0];
        float4 b = *(const float4*)&w_sh[k][oo0];
        float av[4] = {a.x, a.y, a.z, a.w};
        float bv[4] = {b.x, b.y, b.z, b.w};
#pragma unroll
        for (int i = 0; i < 4; i++)
#pragma unroll
            for (int jj2 = 0; jj2 < 4; jj2++) acc[i][jj2] += av[i] * bv[jj2];
    }

    float bo[4]; int mk[4];
#pragma unroll
    for (int jj2 = 0; jj2 < 4; jj2++) {
        int o = o0 + oo0 + jj2;
        bo[jj2] = b_out[o];
        mk[jj2] = mask[o];
    }
#pragma unroll
    for (int i = 0; i < 4; i++) {
        float r4[4];
#pragma unroll
        for (int jj2 = 0; jj2 < 4; jj2++) {
            float v = acc[i][jj2] + bo[jj2];
            r4[jj2] = (mk[jj2] == 0) ? -1000000000.0f : v;
        }
        float4 res = make_float4(r4[0], r4[1], r4[2], r4[3]);
        *(float4*)(out + (size_t)(t0 + tt0 + i) * JJ + o0 + oo0) = res;
    }
}

// =====================================================================
extern "C" void kernel_launch(void* const* d_in, const int* in_sizes, int n_in,
                              void* d_out, int out_size) {
    const float* states = (const float*)d_in[0];
    const float* h0     = (const float*)d_in[1];
    const float* w_ih   = (const float*)d_in[2];
    const float* w_hh   = (const float*)d_in[3];
    const float* b_ih   = (const float*)d_in[4];
    const float* b_hh   = (const float*)d_in[5];
    const float* w_out  = (const float*)d_in[6];
    const float* b_out  = (const float*)d_in[7];
    const int*   mask   = (const int*)d_in[8];
    float* out = (float*)d_out;

    gi_kernel<<<1024, 192>>>(states, w_ih, b_ih);
    scan_kernel<<<1, 128>>>(h0, w_hh, b_hh, out + (size_t)T_STEPS * JJ);
    out_kernel<<<dim3(512, 16), 256>>>(w_out, b_out, mask, out);
}

// round 2
// speedup vs baseline: 1.0688x; 1.0688x over previous
#include <cuda_runtime.h>

#define T_STEPS 32768
#define DIM     256
#define HID     64
#define G3      192      // 3*HID
#define JJ      1024     // J*J
#define CH      4        // gi prefetch chunk (must be even)

// Scratch (no runtime allocation allowed)
__device__ float g_gi[(T_STEPS + CH) * G3];   // ~25 MB, padded for prefetch overrun
__device__ float g_hs[T_STEPS * HID];         // 8 MB

typedef unsigned long long u64;

// ---------------- f32x2 helpers ----------------
__device__ __forceinline__ u64 pack2(float lo, float hi) {
    u64 r; asm("mov.b64 %0, {%1, %2};" : "=l"(r) : "f"(lo), "f"(hi)); return r;
}
__device__ __forceinline__ void unpack2(u64 v, float& lo, float& hi) {
    asm("mov.b64 {%0, %1}, %2;" : "=f"(lo), "=f"(hi) : "l"(v));
}
__device__ __forceinline__ u64 fma2(u64 a, u64 b, u64 c) {
    u64 d; asm("fma.rn.f32x2 %0, %1, %2, %3;" : "=l"(d) : "l"(a), "l"(b), "l"(c)); return d;
}
__device__ __forceinline__ u64 add2(u64 a, u64 b) {
    u64 d; asm("add.rn.f32x2 %0, %1, %2;" : "=l"(d) : "l"(a), "l"(b)); return d;
}
__device__ __forceinline__ float red2(u64 v) { float a, b; unpack2(v, a, b); return a + b; }

__device__ __forceinline__ float sigf(float x) {
    return __fdividef(1.0f, 1.0f + __expf(-x));
}
__device__ __forceinline__ float tanh_fast(float x) {
    return 1.0f - __fdividef(2.0f, __expf(2.0f * x) + 1.0f);
}

// =====================================================================
// Kernel 1: gi[t,g] = b_ih[g] + (g<128 ? b_hh[g] : 0) + sum_d x[t,d]*w_ih[g,d]
// (b_hh for r,z rows folded here; n-row b_hh enters inside the scan)
// 96 threads, 2 g per thread, 32 t-rows per block -> FMA:LDS ratio 4.
// =====================================================================
__global__ __launch_bounds__(96) void gi_kernel(const float* __restrict__ states,
                                                const float* __restrict__ w_ih,
                                                const float* __restrict__ b_ih,
                                                const float* __restrict__ b_hh) {
    __shared__ float xs[32][36];           // [dd][tt], padded
    const int tid = threadIdx.x;
    const int t0  = blockIdx.x * 32;
    const int g0  = tid;
    const int g1  = tid + 96;

    u64 acc0[16], acc1[16];
#pragma unroll
    for (int q = 0; q < 16; q++) { acc0[q] = 0ULL; acc1[q] = 0ULL; }

    const float* w0r = w_ih + (size_t)g0 * DIM;
    const float* w1r = w_ih + (size_t)g1 * DIM;

    for (int d0 = 0; d0 < DIM; d0 += 32) {
        __syncthreads();
        for (int i = tid; i < 1024; i += 96) {
            int dd = i & 31, tt = i >> 5;
            xs[dd][tt] = states[(size_t)(t0 + tt) * (DIM + 3) + d0 + dd];
        }
        __syncthreads();

#pragma unroll
        for (int ds = 0; ds < 32; ds += 8) {
            float wa[8], wb[8];
#pragma unroll
            for (int k = 0; k < 8; k++) { wa[k] = w0r[d0 + ds + k]; wb[k] = w1r[d0 + ds + k]; }
#pragma unroll
            for (int k = 0; k < 8; k++) {
                const float4* xr = (const float4*)xs[ds + k];
                u64 wpa = pack2(wa[k], wa[k]);
                u64 wpb = pack2(wb[k], wb[k]);
#pragma unroll
                for (int q = 0; q < 8; q++) {
                    float4 v = xr[q];
                    u64 x01 = pack2(v.x, v.y);
                    u64 x23 = pack2(v.z, v.w);
                    acc0[2 * q + 0] = fma2(x01, wpa, acc0[2 * q + 0]);
                    acc0[2 * q + 1] = fma2(x23, wpa, acc0[2 * q + 1]);
                    acc1[2 * q + 0] = fma2(x01, wpb, acc1[2 * q + 0]);
                    acc1[2 * q + 1] = fma2(x23, wpb, acc1[2 * q + 1]);
                }
            }
        }
    }

    const float bA = b_ih[g0] + (g0 < 128 ? b_hh[g0] : 0.0f);
    const float bB = b_ih[g1] + (g1 < 128 ? b_hh[g1] : 0.0f);
#pragma unroll
    for (int q = 0; q < 16; q++) {
        float a, c; unpack2(acc0[q], a, c);
        g_gi[(size_t)(t0 + 2 * q + 0) * G3 + g0] = a + bA;
        g_gi[(size_t)(t0 + 2 * q + 1) * G3 + g0] = c + bA;
        unpack2(acc1[q], a, c);
        g_gi[(size_t)(t0 + 2 * q + 0) * G3 + g1] = a + bB;
        g_gi[(size_t)(t0 + 2 * q + 1) * G3 + g1] = c + bB;
    }
}

// =====================================================================
// Kernel 2: sequential GRU scan. ONE block, 128 threads (4 warps).
// Lane pair (2m, 2m+1) owns h-index j = warp*16 + m, split by k-half:
//   even lane: k=0..31 of r-, z-, n-dots; odd lane: k=32..63.
// Partial sums combined with 3 parallel shfl.xor(1); both lanes then
// compute the activations redundantly (no post-activation exchange).
// One __syncthreads per step (double-buffered h in shared); hprev in reg.
// =====================================================================
__global__ __launch_bounds__(128, 1) void scan_kernel(const float* __restrict__ h0,
                                                      const float* __restrict__ w_hh,
                                                      const float* __restrict__ b_hh,
                                                      float* __restrict__ h_final) {
    __shared__ float hbuf[2][HID];

    const int tid  = threadIdx.x;
    const int w    = tid >> 5;
    const int lane = tid & 31;
    const int m    = lane >> 1;
    const int j    = w * 16 + m;
    const int half = lane & 1;               // 0: k 0..31, 1: k 32..63

    // Weight half-rows in registers (f32x2 packed): r=j, z=64+j, n=128+j
    u64 wr[16], wz[16], wn[16];
    {
        const u64* pr = (const u64*)(w_hh + (size_t)j * HID)         + half * 16;
        const u64* pz = (const u64*)(w_hh + (size_t)(64 + j) * HID)  + half * 16;
        const u64* pn = (const u64*)(w_hh + (size_t)(128 + j) * HID) + half * 16;
#pragma unroll
        for (int k = 0; k < 16; k++) { wr[k] = pr[k]; wz[k] = pz[k]; wn[k] = pn[k]; }
    }
    const float bn = b_hh[128 + j];          // n-gate hh bias (r,z folded into gi)
    const u64 bn_init = half ? 0ULL : pack2(bn, 0.0f);

    if (tid < HID) hbuf[0][tid] = h0[tid];
    float hcur = h0[j];

    const float* gr = g_gi + j;
    const float* gz = g_gi + 64 + j;
    const float* gn = g_gi + 128 + j;

    float grn[CH], gzn[CH], gnn[CH];
#pragma unroll
    for (int k = 0; k < CH; k++) {
        grn[k] = gr[(size_t)k * G3];
        gzn[k] = gz[(size_t)k * G3];
        gnn[k] = gn[(size_t)k * G3];
    }
    __syncthreads();

    for (int s0 = 0; s0 < T_STEPS; s0 += CH) {
        float grc[CH], gzc[CH], gnc[CH];
#pragma unroll
        for (int k = 0; k < CH; k++) { grc[k] = grn[k]; gzc[k] = gzn[k]; gnc[k] = gnn[k]; }
        {   // prefetch next chunk (padded tail is harmless)
            const size_t nb = (size_t)(s0 + CH) * G3;
#pragma unroll
            for (int k = 0; k < CH; k++) {
                grn[k] = gr[nb + (size_t)k * G3];
                gzn[k] = gz[nb + (size_t)k * G3];
                gnn[k] = gn[nb + (size_t)k * G3];
            }
        }

#pragma unroll
        for (int ss = 0; ss < CH; ss++) {
            const int p = ss & 1;

            const float4* hp = (const float4*)(hbuf[p] + half * 32);  // this lane's k-half
            u64 ar0 = 0, ar1 = 0, az0 = 0, az1 = 0, an0 = bn_init, an1 = 0;
#pragma unroll
            for (int q = 0; q < 8; q++) {
                float4 v = hp[q];
                u64 h01 = pack2(v.x, v.y);
                u64 h23 = pack2(v.z, v.w);
                if (q & 1) {
                    ar1 = fma2(wr[2 * q], h01, ar1); ar1 = fma2(wr[2 * q + 1], h23, ar1);
                    az1 = fma2(wz[2 * q], h01, az1); az1 = fma2(wz[2 * q + 1], h23, az1);
                    an1 = fma2(wn[2 * q], h01, an1); an1 = fma2(wn[2 * q + 1], h23, an1);
                } else {
                    ar0 = fma2(wr[2 * q], h01, ar0); ar0 = fma2(wr[2 * q + 1], h23, ar0);
                    az0 = fma2(wz[2 * q], h01, az0); az0 = fma2(wz[2 * q + 1], h23, az0);
                    an0 = fma2(wn[2 * q], h01, an0); an0 = fma2(wn[2 * q + 1], h23, an0);
                }
            }
            float sr = red2(add2(ar0, ar1));
            float sz = red2(add2(az0, az1));
            float sn = red2(add2(an0, an1));
            sr += __shfl_xor_sync(0xffffffffu, sr, 1);
            sz += __shfl_xor_sync(0xffffffffu, sz, 1);
            sn += __shfl_xor_sync(0xffffffffu, sn, 1);

            const float z   = sigf(gzc[ss] + sz);
            const float zh  = z * hcur;
            const float omz = 1.0f - z;
            const float r   = sigf(grc[ss] + sr);
            const float n   = tanh_fast(fmaf(r, sn, gnc[ss]));
            const float hnew = fmaf(n, omz, zh);
            hcur = hnew;

            if (half) {
                hbuf[p ^ 1][j] = hnew;
                g_hs[(size_t)(s0 + ss) * HID + j] = hnew;
            }
            __syncthreads();
        }
    }
    if (half) h_final[j] = hcur;
}

// =====================================================================
// Kernel 3: logits[t,o] = mask[o] ? hs[t,:]·w_out[o,:] + b_out[o] : -1e9
// =====================================================================
__global__ __launch_bounds__(256) void out_kernel(const float* __restrict__ w_out,
                                                  const float* __restrict__ b_out,
                                                  const int* __restrict__ mask,
                                                  float* __restrict__ out) {
    __shared__ float hs_sh[64][68];   // [k][t]
    __shared__ float w_sh[64][68];    // [k][o]

    const int tid = threadIdx.x;
    const int t0  = blockIdx.x * 64;
    const int o0  = blockIdx.y * 64;

#pragma unroll
    for (int q = 0; q < 4; q++) {
        int i  = tid + q * 256;
        int rr = i >> 4;
        int kq = i & 15;
        float4 v = *(const float4*)(g_hs + (size_t)(t0 + rr) * HID + kq * 4);
        hs_sh[kq * 4 + 0][rr] = v.x;
        hs_sh[kq * 4 + 1][rr] = v.y;
        hs_sh[kq * 4 + 2][rr] = v.z;
        hs_sh[kq * 4 + 3][rr] = v.w;
        float4 wv = *(const float4*)(w_out + (size_t)(o0 + rr) * HID + kq * 4);
        w_sh[kq * 4 + 0][rr] = wv.x;
        w_sh[kq * 4 + 1][rr] = wv.y;
        w_sh[kq * 4 + 2][rr] = wv.z;
        w_sh[kq * 4 + 3][rr] = wv.w;
    }
    __syncthreads();

    const int oo0 = (tid & 15) * 4;
    const int tt0 = (tid >> 4) * 4;

    float acc[4][4];
#pragma unroll
    for (int i = 0; i < 4; i++)
#pragma unroll
        for (int jj2 = 0; jj2 < 4; jj2++) acc[i][jj2] = 0.0f;

#pragma unroll
    for (int k = 0; k < 64; k++) {
        float4 a = *(const float4*)&hs_sh[k][tt0];
        float4 b = *(const float4*)&w_sh[k][oo0];
        float av[4] = {a.x, a.y, a.z, a.w};
        float bv[4] = {b.x, b.y, b.z, b.w};
#pragma unroll
        for (int i = 0; i < 4; i++)
#pragma unroll
            for (int jj2 = 0; jj2 < 4; jj2++) acc[i][jj2] += av[i] * bv[jj2];
    }

    float bo[4]; int mk[4];
#pragma unroll
    for (int jj2 = 0; jj2 < 4; jj2++) {
        int o = o0 + oo0 + jj2;
        bo[jj2] = b_out[o];
        mk[jj2] = mask[o];
    }
#pragma unroll
    for (int i = 0; i < 4; i++) {
        float r4[4];
#pragma unroll
        for (int jj2 = 0; jj2 < 4; jj2++) {
            float v = acc[i][jj2] + bo[jj2];
            r4[jj2] = (mk[jj2] == 0) ? -1000000000.0f : v;
        }
        float4 res = make_float4(r4[0], r4[1], r4[2], r4[3]);
        *(float4*)(out + (size_t)(t0 + tt0 + i) * JJ + o0 + oo0) = res;
    }
}

// =====================================================================
extern "C" void kernel_launch(void* const* d_in, const int* in_sizes, int n_in,
                              void* d_out, int out_size) {
    const float* states = (const float*)d_in[0];
    const float* h0     = (const float*)d_in[1];
    const float* w_ih   = (const float*)d_in[2];
    const float* w_hh   = (const float*)d_in[3];
    const float* b_ih   = (const float*)d_in[4];
    const float* b_hh   = (const float*)d_in[5];
    const float* w_out  = (const float*)d_in[6];
    const float* b_out  = (const float*)d_in[7];
    const int*   mask   = (const int*)d_in[8];
    float* out = (float*)d_out;

    gi_kernel<<<1024, 96>>>(states, w_ih, b_ih, b_hh);
    scan_kernel<<<1, 128>>>(h0, w_hh, b_hh, out + (size_t)T_STEPS * JJ);
    out_kernel<<<dim3(512, 16), 256>>>(w_out, b_out, mask, out);
}